// round 6
// baseline (speedup 1.0000x reference)
#include <cuda_runtime.h>
#include <cuda_fp16.h>
#include <cstdint>

// ===================== problem constants =====================
#define MTOK   8192
#define KDIM   4096
#define NDIM   4096
#define BM     128
#define BN     256
#define BK     32
#define KIT    (KDIM / BK)          // 128
#define STAGE_BYTES 24576           // A 8KB + B 16KB per stage
#define SMEM_GEMM   (4 * STAGE_BYTES)   // 96 KB

// ===================== scratch (device globals; no runtime alloc) =====================
__device__ __half g_A[(size_t)MTOK * KDIM];   // quantized activations (exact ints in fp16)
__device__ __half g_W[(size_t)NDIM * KDIM];   // weights in fp16
__device__ float  g_scale[MTOK];              // per-token scale

// ===================== helpers =====================
__device__ __forceinline__ uint32_t smem_u32(const void* p) {
    uint32_t a;
    asm("{ .reg .u64 t; cvta.to.shared.u64 t, %1; cvt.u32.u64 %0, t; }" : "=r"(a) : "l"(p));
    return a;
}

// rows of 64B (32 halfs); XOR-swizzle 16B granules so ldmatrix phases are conflict-free
#define SWZ(row, g) ((uint32_t)((row) * 64 + ((((g) ^ (((row) >> 1) & 3))) << 4)))

#define CP_ASYNC16(dst, src) \
    asm volatile("cp.async.cg.shared.global [%0], [%1], 16;" :: "r"(dst), "l"(src) : "memory")
#define CP_COMMIT() asm volatile("cp.async.commit_group;" ::: "memory")
#define CP_WAIT2()  asm volatile("cp.async.wait_group 2;" ::: "memory")

#define LDSM4(r, addr)                                                              \
    asm volatile("ldmatrix.sync.aligned.m8n8.x4.shared.b16 {%0,%1,%2,%3}, [%4];"    \
        : "=r"((r)[0]), "=r"((r)[1]), "=r"((r)[2]), "=r"((r)[3]) : "r"(addr))

#define MMA16816(d, a, b0, b1)                                                      \
    asm volatile("mma.sync.aligned.m16n8k16.row.col.f32.f16.f16.f32 "               \
        "{%0,%1,%2,%3},{%4,%5,%6,%7},{%8,%9},{%0,%1,%2,%3};"                        \
        : "+f"((d)[0]), "+f"((d)[1]), "+f"((d)[2]), "+f"((d)[3])                    \
        : "r"((a)[0]), "r"((a)[1]), "r"((a)[2]), "r"((a)[3]), "r"(b0), "r"(b1))

// ===================== kernel 1: fused prep (activations + weights) =====================
// blocks [0, 8192): one token each (sparsity + absmax quant)
// blocks [8192, 9216): weight fp32->fp16, 4096 float4 per block
__global__ void __launch_bounds__(128) prep_kernel(const float* __restrict__ x,
                                                   const float* __restrict__ ss,
                                                   const float* __restrict__ w) {
    const int tid = threadIdx.x;

    if (blockIdx.x >= MTOK) {
        // ---- weight convert: contiguous 4096-float4 chunk ----
        const int base = (blockIdx.x - MTOK) * 4096;
        uint2* dst = reinterpret_cast<uint2*>(g_W);
        const float4* src = reinterpret_cast<const float4*>(w);
#pragma unroll
        for (int i = 0; i < 32; ++i) {
            const int idx = base + i * 128 + tid;
            float4 v = src[idx];
            __half2 h0 = __floats2half2_rn(v.x, v.y);
            __half2 h1 = __floats2half2_rn(v.z, v.w);
            uint2 pk;
            pk.x = *reinterpret_cast<uint32_t*>(&h0);
            pk.y = *reinterpret_cast<uint32_t*>(&h1);
            dst[idx] = pk;
        }
        return;
    }

    // ---- activation: 2:4 sparsity + per-token absmax quant ----
    __shared__ float red[4];
    const int t   = blockIdx.x;
    const int lid = tid & 31, wid = tid >> 5;

    const float4* xr  = reinterpret_cast<const float4*>(x + (size_t)t * KDIM);
    const float4* ssr = reinterpret_cast<const float4*>(ss);

    float4 kept[8];
    float kmax = 0.0f;
#pragma unroll
    for (int j = 0; j < 8; ++j) {
        const int g = j * 128 + tid;            // group id 0..1023
        float4 xv = xr[g];
        float4 sv = ssr[g];
        float mm[4] = { fabsf(xv.x) * sv.x, fabsf(xv.y) * sv.y,
                        fabsf(xv.z) * sv.z, fabsf(xv.w) * sv.w };
        // two smallest, ties -> lowest index (matches jax top_k(-m, 2) stability)
        int i1 = 0;
#pragma unroll
        for (int k = 1; k < 4; ++k) if (mm[k] < mm[i1]) i1 = k;
        int i2 = -1;
#pragma unroll
        for (int k = 0; k < 4; ++k) {
            if (k == i1) continue;
            if (i2 < 0 || mm[k] < mm[i2]) i2 = k;
        }
        float v[4] = { xv.x, xv.y, xv.z, xv.w };
        v[i1] = 0.0f; v[i2] = 0.0f;
        kept[j] = make_float4(v[0], v[1], v[2], v[3]);
        kmax = fmaxf(kmax, fmaxf(fmaxf(fabsf(v[0]), fabsf(v[1])),
                                 fmaxf(fabsf(v[2]), fabsf(v[3]))));
    }
#pragma unroll
    for (int off = 16; off; off >>= 1) kmax = fmaxf(kmax, __shfl_xor_sync(~0u, kmax, off));
    if (lid == 0) red[wid] = kmax;
    __syncthreads();
    const float amax  = fmaxf(fmaxf(red[0], red[1]), fmaxf(red[2], red[3]));
    const float denom = fmaxf(amax, 1e-5f);
    const float scale = denom / 127.0f;
    const float inv   = __fdiv_rn(127.0f, denom);   // one IEEE div per thread
    if (tid == 0) g_scale[t] = scale;

    uint2* dst = reinterpret_cast<uint2*>(g_A + (size_t)t * KDIM);
#pragma unroll
    for (int j = 0; j < 8; ++j) {
        const int g = j * 128 + tid;
        // rintf = round-half-even = jnp.round; inv-mul deviates <=1ulp from IEEE div
        float q0 = rintf(kept[j].x * inv);
        float q1 = rintf(kept[j].y * inv);
        float q2 = rintf(kept[j].z * inv);
        float q3 = rintf(kept[j].w * inv);
        __half2 p0 = __floats2half2_rn(q0, q1);   // exact: |q|<=127 integer
        __half2 p1 = __floats2half2_rn(q2, q3);
        uint2 pk;
        pk.x = *reinterpret_cast<uint32_t*>(&p0);
        pk.y = *reinterpret_cast<uint32_t*>(&p1);
        dst[g] = pk;
    }
}

// ===================== kernel 2: mma.sync fp16 GEMM =====================
// CTA 128x256x32, 8 warps (2m x 4n) each 64x64, 4-stage cp.async pipeline
__global__ void __launch_bounds__(256, 1)
gemm_kernel(const float* __restrict__ bias, float* __restrict__ out) {
    extern __shared__ char smem[];
    const uint32_t sb = smem_u32(smem);
    const int tid  = threadIdx.x, lane = tid & 31, wid = tid >> 5;
    const int m0 = blockIdx.x * BM;
    const int n0 = blockIdx.y * BN;
    const int mw = (wid & 1) * 64;      // warp m offset in CTA tile
    const int nw = (wid >> 1) * 64;     // warp n offset

    // cp.async: per stage A = 512 granules (2/thread), B = 1024 granules (4/thread)
    const int rA = tid >> 2, gA = tid & 3;
    const uint32_t dA0 = SWZ(rA, gA);              // rows rA and rA+64 share swizzle offset delta 64*64
    const __half* srcA0 = g_A + (size_t)(m0 + rA) * KDIM + gA * 8;
    const __half* srcB0 = g_W + (size_t)(n0 + rA) * KDIM + gA * 8;
    const size_t rowSkip = (size_t)64 * KDIM;

    float acc[4][8][4];
#pragma unroll
    for (int i = 0; i < 4; ++i)
#pragma unroll
        for (int j = 0; j < 8; ++j)
#pragma unroll
            for (int k = 0; k < 4; ++k) acc[i][j][k] = 0.0f;

    // prologue: fill stages 0..2
#pragma unroll
    for (int s = 0; s < 3; ++s) {
        const uint32_t a = sb + s * STAGE_BYTES;
        const uint32_t b = a + 8192;
        const int ko = s * BK;
        CP_ASYNC16(a + dA0,        srcA0 + ko);
        CP_ASYNC16(a + dA0 + 4096, srcA0 + rowSkip + ko);
        CP_ASYNC16(b + dA0,         srcB0 + ko);
        CP_ASYNC16(b + dA0 + 4096,  srcB0 + rowSkip + ko);
        CP_ASYNC16(b + dA0 + 8192,  srcB0 + 2 * rowSkip + ko);
        CP_ASYNC16(b + dA0 + 12288, srcB0 + 3 * rowSkip + ko);
        CP_COMMIT();
    }

    for (int it = 0; it < KIT; ++it) {
        CP_WAIT2();
        __syncthreads();

        // prefetch stage it+3 (overwrites stage it-1; everyone is past it-1 after the sync)
        if (it + 3 < KIT) {
            const uint32_t a = sb + ((it + 3) & 3) * STAGE_BYTES;
            const uint32_t b = a + 8192;
            const int ko = (it + 3) * BK;
            CP_ASYNC16(a + dA0,        srcA0 + ko);
            CP_ASYNC16(a + dA0 + 4096, srcA0 + rowSkip + ko);
            CP_ASYNC16(b + dA0,         srcB0 + ko);
            CP_ASYNC16(b + dA0 + 4096,  srcB0 + rowSkip + ko);
            CP_ASYNC16(b + dA0 + 8192,  srcB0 + 2 * rowSkip + ko);
            CP_ASYNC16(b + dA0 + 12288, srcB0 + 3 * rowSkip + ko);
        }
        CP_COMMIT();

        const uint32_t sA = sb + (it & 3) * STAGE_BYTES;
        const uint32_t sB = sA + 8192;

#pragma unroll
        for (int ks = 0; ks < 2; ++ks) {
            uint32_t aF[4][4], bF[4][4];
#pragma unroll
            for (int mt = 0; mt < 4; ++mt) {
                const int row = mw + mt * 16 + (lane & 15);
                const int g   = ks * 2 + (lane >> 4);
                LDSM4(aF[mt], sA + SWZ(row, g));
            }
#pragma unroll
            for (int nt = 0; nt < 4; ++nt) {
                const int row = nw + nt * 16 + (lane & 7) + ((lane >> 4) << 3);
                const int g   = ks * 2 + ((lane >> 3) & 1);
                LDSM4(bF[nt], sB + SWZ(row, g));
            }
#pragma unroll
            for (int mt = 0; mt < 4; ++mt)
#pragma unroll
                for (int nt = 0; nt < 4; ++nt) {
                    MMA16816(acc[mt][2 * nt],     aF[mt], bF[nt][0], bF[nt][1]);
                    MMA16816(acc[mt][2 * nt + 1], aF[mt], bF[nt][2], bF[nt][3]);
                }
        }
        __syncthreads();
    }

    // epilogue: scale * acc + bias, direct float2 stores
#pragma unroll
    for (int mt = 0; mt < 4; ++mt) {
        const int m = m0 + mw + mt * 16 + (lane >> 2);
        const float s0 = g_scale[m];
        const float s1 = g_scale[m + 8];
#pragma unroll
        for (int nt = 0; nt < 8; ++nt) {
            const int n = n0 + nw + nt * 8 + (lane & 3) * 2;
            const float2 b2 = *reinterpret_cast<const float2*>(bias + n);
            float2 o0, o1;
            o0.x = acc[mt][nt][0] * s0 + b2.x;
            o0.y = acc[mt][nt][1] * s0 + b2.y;
            o1.x = acc[mt][nt][2] * s1 + b2.x;
            o1.y = acc[mt][nt][3] * s1 + b2.y;
            *reinterpret_cast<float2*>(out + (size_t)m * NDIM + n)       = o0;
            *reinterpret_cast<float2*>(out + (size_t)(m + 8) * NDIM + n) = o1;
        }
    }
}

// ===================== launch =====================
extern "C" void kernel_launch(void* const* d_in, const int* in_sizes, int n_in,
                              void* d_out, int out_size) {
    const float* x    = static_cast<const float*>(d_in[0]);
    const float* w    = static_cast<const float*>(d_in[1]);
    const float* bias = static_cast<const float*>(d_in[2]);
    const float* ss   = static_cast<const float*>(d_in[3]);
    float* out = static_cast<float*>(d_out);

    // 8192 token blocks + 1024 weight-convert blocks, one kernel -> 2 launches/call
    prep_kernel<<<MTOK + 1024, 128>>>(x, ss, w);

    cudaFuncSetAttribute(gemm_kernel, cudaFuncAttributeMaxDynamicSharedMemorySize, SMEM_GEMM);
    dim3 grid(MTOK / BM, NDIM / BN);   // 64 x 16
    gemm_kernel<<<grid, 256, SMEM_GEMM>>>(bias, out);
}

// round 9
// speedup vs baseline: 1.1862x; 1.1862x over previous
#include <cuda_runtime.h>
#include <cuda_fp16.h>
#include <cstdint>

// ===================== problem constants =====================
#define MTOK   8192
#define KDIM   4096
#define NDIM   4096
#define BM     128
#define BN     128
#define BK     64
#define KIT    (KDIM / BK)          // 64
#define STAGE_BYTES 32768           // A 16KB + B 16KB per stage
#define NSTAGE 3
#define SMEM_GEMM   (NSTAGE * STAGE_BYTES)   // 96 KB -> 2 CTAs/SM

// ===================== scratch (device globals; no runtime alloc) =====================
__device__ __half g_A[(size_t)MTOK * KDIM];   // quantized activations (exact ints in fp16)
__device__ __half g_W[(size_t)NDIM * KDIM];   // weights in fp16
__device__ float  g_scale[MTOK];              // per-token scale

// ===================== helpers =====================
__device__ __forceinline__ uint32_t smem_u32(const void* p) {
    uint32_t a;
    asm("{ .reg .u64 t; cvta.to.shared.u64 t, %1; cvt.u32.u64 %0, t; }" : "=r"(a) : "l"(p));
    return a;
}

// rows of 128B (64 halfs); XOR-swizzle the 8 16B granules by row&7 -> ldmatrix conflict-free
#define SWZ(row, g) ((uint32_t)((row) * 128 + ((((g) ^ ((row) & 7))) << 4)))

#define CP_ASYNC16(dst, src) \
    asm volatile("cp.async.cg.shared.global [%0], [%1], 16;" :: "r"(dst), "l"(src) : "memory")
#define CP_COMMIT() asm volatile("cp.async.commit_group;" ::: "memory")
#define CP_WAIT1()  asm volatile("cp.async.wait_group 1;" ::: "memory")

#define LDSM4(r, addr)                                                              \
    asm volatile("ldmatrix.sync.aligned.m8n8.x4.shared.b16 {%0,%1,%2,%3}, [%4];"    \
        : "=r"((r)[0]), "=r"((r)[1]), "=r"((r)[2]), "=r"((r)[3]) : "r"(addr))

#define MMA16816(d, a, b0, b1)                                                      \
    asm volatile("mma.sync.aligned.m16n8k16.row.col.f32.f16.f16.f32 "               \
        "{%0,%1,%2,%3},{%4,%5,%6,%7},{%8,%9},{%0,%1,%2,%3};"                        \
        : "+f"((d)[0]), "+f"((d)[1]), "+f"((d)[2]), "+f"((d)[3])                    \
        : "r"((a)[0]), "r"((a)[1]), "r"((a)[2]), "r"((a)[3]), "r"(b0), "r"(b1))

// ===================== kernel 1: fused prep (activations + weights) =====================
// blocks [0, 8192): one token each (sparsity + absmax quant)
// blocks [8192, 9216): weight fp32->fp16, 4096 float4 per block
__global__ void __launch_bounds__(128) prep_kernel(const float* __restrict__ x,
                                                   const float* __restrict__ ss,
                                                   const float* __restrict__ w) {
    const int tid = threadIdx.x;

    if (blockIdx.x >= MTOK) {
        const int base = (blockIdx.x - MTOK) * 4096;
        uint2* dst = reinterpret_cast<uint2*>(g_W);
        const float4* src = reinterpret_cast<const float4*>(w);
#pragma unroll
        for (int i = 0; i < 32; ++i) {
            const int idx = base + i * 128 + tid;
            float4 v = src[idx];
            __half2 h0 = __floats2half2_rn(v.x, v.y);
            __half2 h1 = __floats2half2_rn(v.z, v.w);
            uint2 pk;
            pk.x = *reinterpret_cast<uint32_t*>(&h0);
            pk.y = *reinterpret_cast<uint32_t*>(&h1);
            dst[idx] = pk;
        }
        return;
    }

    __shared__ float red[4];
    const int t   = blockIdx.x;
    const int lid = tid & 31, wid = tid >> 5;

    const float4* xr  = reinterpret_cast<const float4*>(x + (size_t)t * KDIM);
    const float4* ssr = reinterpret_cast<const float4*>(ss);

    float4 kept[8];
    float kmax = 0.0f;
#pragma unroll
    for (int j = 0; j < 8; ++j) {
        const int g = j * 128 + tid;            // group id 0..1023
        float4 xv = xr[g];
        float4 sv = ssr[g];
        float mm[4] = { fabsf(xv.x) * sv.x, fabsf(xv.y) * sv.y,
                        fabsf(xv.z) * sv.z, fabsf(xv.w) * sv.w };
        int i1 = 0;
#pragma unroll
        for (int k = 1; k < 4; ++k) if (mm[k] < mm[i1]) i1 = k;
        int i2 = -1;
#pragma unroll
        for (int k = 0; k < 4; ++k) {
            if (k == i1) continue;
            if (i2 < 0 || mm[k] < mm[i2]) i2 = k;
        }
        float v[4] = { xv.x, xv.y, xv.z, xv.w };
        v[i1] = 0.0f; v[i2] = 0.0f;
        kept[j] = make_float4(v[0], v[1], v[2], v[3]);
        kmax = fmaxf(kmax, fmaxf(fmaxf(fabsf(v[0]), fabsf(v[1])),
                                 fmaxf(fabsf(v[2]), fabsf(v[3]))));
    }
#pragma unroll
    for (int off = 16; off; off >>= 1) kmax = fmaxf(kmax, __shfl_xor_sync(~0u, kmax, off));
    if (lid == 0) red[wid] = kmax;
    __syncthreads();
    const float amax  = fmaxf(fmaxf(red[0], red[1]), fmaxf(red[2], red[3]));
    const float denom = fmaxf(amax, 1e-5f);
    const float scale = denom / 127.0f;
    const float inv   = __fdiv_rn(127.0f, denom);
    if (tid == 0) g_scale[t] = scale;

    uint2* dst = reinterpret_cast<uint2*>(g_A + (size_t)t * KDIM);
#pragma unroll
    for (int j = 0; j < 8; ++j) {
        const int g = j * 128 + tid;
        float q0 = rintf(kept[j].x * inv);
        float q1 = rintf(kept[j].y * inv);
        float q2 = rintf(kept[j].z * inv);
        float q3 = rintf(kept[j].w * inv);
        __half2 p0 = __floats2half2_rn(q0, q1);
        __half2 p1 = __floats2half2_rn(q2, q3);
        uint2 pk;
        pk.x = *reinterpret_cast<uint32_t*>(&p0);
        pk.y = *reinterpret_cast<uint32_t*>(&p1);
        dst[g] = pk;
    }
}

// ===================== kernel 2: mma.sync fp16 GEMM =====================
// CTA 128x128x64, 8 warps (4m x 2n) each 32x64, 3-stage cp.async, 2 CTAs/SM,
// ONE barrier per K-iteration.
__global__ void __launch_bounds__(256, 2)
gemm_kernel(const float* __restrict__ bias, float* __restrict__ out) {
    extern __shared__ char smem[];
    const uint32_t sb = smem_u32(smem);
    const int tid  = threadIdx.x, lane = tid & 31, wid = tid >> 5;
    const int m0 = blockIdx.x * BM;
    const int n0 = blockIdx.y * BN;
    const int mw = (wid & 3) * 32;      // warp m offset
    const int nw = (wid >> 2) * 64;     // warp n offset

    // cp.async: per stage, A = 1024 granules of 16B (4/thread), B = 1024 (4/thread)
    const int gIdx = tid;                         // granule base: tid + i*256
    const int rA = gIdx >> 3, gA = gIdx & 7;      // row 0..31 (+i*32), granule in row
    const uint32_t dSw = SWZ(rA, gA);             // row r+32 adds 32*128 bytes, swizzle col unchanged only if (r&7) same -> true for +32
    const __half* srcA0 = g_A + (size_t)(m0 + rA) * KDIM + gA * 8;
    const __half* srcB0 = g_W + (size_t)(n0 + rA) * KDIM + gA * 8;
    const size_t rowSkip = (size_t)32 * KDIM;

    float acc[2][8][4];
#pragma unroll
    for (int i = 0; i < 2; ++i)
#pragma unroll
        for (int j = 0; j < 8; ++j)
#pragma unroll
            for (int k = 0; k < 4; ++k) acc[i][j][k] = 0.0f;

    // prologue: fill stages 0,1
#pragma unroll
    for (int s = 0; s < 2; ++s) {
        const uint32_t a = sb + s * STAGE_BYTES;
        const uint32_t b = a + 16384;
        const int ko = s * BK;
#pragma unroll
        for (int i = 0; i < 4; ++i) {
            CP_ASYNC16(a + dSw + i * 4096, srcA0 + i * rowSkip + ko);
            CP_ASYNC16(b + dSw + i * 4096, srcB0 + i * rowSkip + ko);
        }
        CP_COMMIT();
    }

    int rdSt = 0, wrSt = 2;   // read stage = it%3, write stage = (it+2)%3
    for (int it = 0; it < KIT; ++it) {
        CP_WAIT1();
        __syncthreads();

        if (it + 2 < KIT) {
            const uint32_t a = sb + wrSt * STAGE_BYTES;
            const uint32_t b = a + 16384;
            const int ko = (it + 2) * BK;
#pragma unroll
            for (int i = 0; i < 4; ++i) {
                CP_ASYNC16(a + dSw + i * 4096, srcA0 + i * rowSkip + ko);
                CP_ASYNC16(b + dSw + i * 4096, srcB0 + i * rowSkip + ko);
            }
        }
        CP_COMMIT();

        const uint32_t sA = sb + rdSt * STAGE_BYTES;
        const uint32_t sB = sA + 16384;

#pragma unroll
        for (int ks = 0; ks < 4; ++ks) {
            uint32_t aF[2][4], bF[4][4];
#pragma unroll
            for (int mt = 0; mt < 2; ++mt) {
                const int row = mw + mt * 16 + (lane & 15);
                const int g   = ks * 2 + (lane >> 4);
                LDSM4(aF[mt], sA + SWZ(row, g));
            }
#pragma unroll
            for (int nt = 0; nt < 4; ++nt) {
                const int row = nw + nt * 16 + (lane & 7) + ((lane >> 4) << 3);
                const int g   = ks * 2 + ((lane >> 3) & 1);
                LDSM4(bF[nt], sB + SWZ(row, g));
            }
#pragma unroll
            for (int mt = 0; mt < 2; ++mt)
#pragma unroll
                for (int nt = 0; nt < 4; ++nt) {
                    MMA16816(acc[mt][2 * nt],     aF[mt], bF[nt][0], bF[nt][1]);
                    MMA16816(acc[mt][2 * nt + 1], aF[mt], bF[nt][2], bF[nt][3]);
                }
        }
        // NO end-of-loop barrier: top-of-loop sync orders stage reads vs overwrite.

        rdSt = (rdSt == 2) ? 0 : rdSt + 1;
        wrSt = (wrSt == 2) ? 0 : wrSt + 1;
    }

    // epilogue: scale * acc + bias, direct float2 stores
#pragma unroll
    for (int mt = 0; mt < 2; ++mt) {
        const int m = m0 + mw + mt * 16 + (lane >> 2);
        const float s0 = g_scale[m];
        const float s1 = g_scale[m + 8];
#pragma unroll
        for (int nt = 0; nt < 8; ++nt) {
            const int n = n0 + nw + nt * 8 + (lane & 3) * 2;
            const float2 b2 = *reinterpret_cast<const float2*>(bias + n);
            float2 o0, o1;
            o0.x = acc[mt][nt][0] * s0 + b2.x;
            o0.y = acc[mt][nt][1] * s0 + b2.y;
            o1.x = acc[mt][nt][2] * s1 + b2.x;
            o1.y = acc[mt][nt][3] * s1 + b2.y;
            *reinterpret_cast<float2*>(out + (size_t)m * NDIM + n)       = o0;
            *reinterpret_cast<float2*>(out + (size_t)(m + 8) * NDIM + n) = o1;
        }
    }
}

// ===================== launch =====================
extern "C" void kernel_launch(void* const* d_in, const int* in_sizes, int n_in,
                              void* d_out, int out_size) {
    const float* x    = static_cast<const float*>(d_in[0]);
    const float* w    = static_cast<const float*>(d_in[1]);
    const float* bias = static_cast<const float*>(d_in[2]);
    const float* ss   = static_cast<const float*>(d_in[3]);
    float* out = static_cast<float*>(d_out);

    prep_kernel<<<MTOK + 1024, 128>>>(x, ss, w);

    cudaFuncSetAttribute(gemm_kernel, cudaFuncAttributeMaxDynamicSharedMemorySize, SMEM_GEMM);
    dim3 grid(MTOK / BM, NDIM / BN);   // 64 x 32
    gemm_kernel<<<grid, 256, SMEM_GEMM>>>(bias, out);
}

// round 14
// speedup vs baseline: 1.2684x; 1.0693x over previous
#include <cuda_runtime.h>
#include <cuda_fp16.h>
#include <cstdint>

// ===================== problem constants =====================
#define MTOK   8192
#define KDIM   4096
#define NDIM   4096
#define BM     128
#define BN     128
#define BK     64
#define KIT    (KDIM / BK)          // 64
#define STAGE_BYTES 32768           // A 16KB + B 16KB per stage
#define NSTAGE 3
#define SMEM_GEMM   (NSTAGE * STAGE_BYTES)   // 96 KB -> 2 CTAs/SM

// ===================== scratch (device globals; no runtime alloc) =====================
__device__ __half g_A[(size_t)MTOK * KDIM];   // quantized activations (exact ints in fp16)
__device__ __half g_W[(size_t)NDIM * KDIM];   // weights in fp16
__device__ float  g_scale[MTOK];              // per-token scale

// ===================== helpers =====================
__device__ __forceinline__ uint32_t smem_u32(const void* p) {
    uint32_t a;
    asm("{ .reg .u64 t; cvta.to.shared.u64 t, %1; cvt.u32.u64 %0, t; }" : "=r"(a) : "l"(p));
    return a;
}

// rows of 128B (64 halfs); XOR-swizzle the 8 16B granules by row&7 -> ldmatrix conflict-free
#define SWZ(row, g) ((uint32_t)((row) * 128 + ((((g) ^ ((row) & 7))) << 4)))

#define CP_ASYNC16(dst, src) \
    asm volatile("cp.async.cg.shared.global [%0], [%1], 16;" :: "r"(dst), "l"(src) : "memory")
#define CP_COMMIT() asm volatile("cp.async.commit_group;" ::: "memory")
#define CP_WAIT1()  asm volatile("cp.async.wait_group 1;" ::: "memory")

#define LDSM4(r, addr)                                                              \
    asm volatile("ldmatrix.sync.aligned.m8n8.x4.shared.b16 {%0,%1,%2,%3}, [%4];"    \
        : "=r"((r)[0]), "=r"((r)[1]), "=r"((r)[2]), "=r"((r)[3]) : "r"(addr))

#define MMA16816(d, a, b0, b1)                                                      \
    asm volatile("mma.sync.aligned.m16n8k16.row.col.f32.f16.f16.f32 "               \
        "{%0,%1,%2,%3},{%4,%5,%6,%7},{%8,%9},{%0,%1,%2,%3};"                        \
        : "+f"((d)[0]), "+f"((d)[1]), "+f"((d)[2]), "+f"((d)[3])                    \
        : "r"((a)[0]), "r"((a)[1]), "r"((a)[2]), "r"((a)[3]), "r"(b0), "r"(b1))

// ===================== kernel 1: fused prep (activations + weights) =====================
// blocks [0, 8192): one token each (sparsity + absmax quant)
// blocks [8192, 9216): weight fp32->fp16, 4096 float4 per block
__global__ void __launch_bounds__(128) prep_kernel(const float* __restrict__ x,
                                                   const float* __restrict__ ss,
                                                   const float* __restrict__ w) {
    const int tid = threadIdx.x;

    if (blockIdx.x >= MTOK) {
        const int base = (blockIdx.x - MTOK) * 4096;
        uint2* dst = reinterpret_cast<uint2*>(g_W);
        const float4* src = reinterpret_cast<const float4*>(w);
#pragma unroll
        for (int i = 0; i < 32; ++i) {
            const int idx = base + i * 128 + tid;
            float4 v = src[idx];
            __half2 h0 = __floats2half2_rn(v.x, v.y);
            __half2 h1 = __floats2half2_rn(v.z, v.w);
            uint2 pk;
            pk.x = *reinterpret_cast<uint32_t*>(&h0);
            pk.y = *reinterpret_cast<uint32_t*>(&h1);
            dst[idx] = pk;
        }
        return;
    }

    __shared__ float red[4];
    const int t   = blockIdx.x;
    const int lid = tid & 31, wid = tid >> 5;

    const float4* xr  = reinterpret_cast<const float4*>(x + (size_t)t * KDIM);
    const float4* ssr = reinterpret_cast<const float4*>(ss);

    float4 kept[8];
    float kmax = 0.0f;
#pragma unroll
    for (int j = 0; j < 8; ++j) {
        const int g = j * 128 + tid;            // group id 0..1023
        float4 xv = xr[g];
        float4 sv = ssr[g];
        float mm[4] = { fabsf(xv.x) * sv.x, fabsf(xv.y) * sv.y,
                        fabsf(xv.z) * sv.z, fabsf(xv.w) * sv.w };
        int i1 = 0;
#pragma unroll
        for (int k = 1; k < 4; ++k) if (mm[k] < mm[i1]) i1 = k;
        int i2 = -1;
#pragma unroll
        for (int k = 0; k < 4; ++k) {
            if (k == i1) continue;
            if (i2 < 0 || mm[k] < mm[i2]) i2 = k;
        }
        float v[4] = { xv.x, xv.y, xv.z, xv.w };
        v[i1] = 0.0f; v[i2] = 0.0f;
        kept[j] = make_float4(v[0], v[1], v[2], v[3]);
        kmax = fmaxf(kmax, fmaxf(fmaxf(fabsf(v[0]), fabsf(v[1])),
                                 fmaxf(fabsf(v[2]), fabsf(v[3]))));
    }
#pragma unroll
    for (int off = 16; off; off >>= 1) kmax = fmaxf(kmax, __shfl_xor_sync(~0u, kmax, off));
    if (lid == 0) red[wid] = kmax;
    __syncthreads();
    const float amax  = fmaxf(fmaxf(red[0], red[1]), fmaxf(red[2], red[3]));
    const float denom = fmaxf(amax, 1e-5f);
    const float scale = denom / 127.0f;
    const float inv   = __fdiv_rn(127.0f, denom);
    if (tid == 0) g_scale[t] = scale;

    uint2* dst = reinterpret_cast<uint2*>(g_A + (size_t)t * KDIM);
#pragma unroll
    for (int j = 0; j < 8; ++j) {
        const int g = j * 128 + tid;
        float q0 = rintf(kept[j].x * inv);
        float q1 = rintf(kept[j].y * inv);
        float q2 = rintf(kept[j].z * inv);
        float q3 = rintf(kept[j].w * inv);
        __half2 p0 = __floats2half2_rn(q0, q1);
        __half2 p1 = __floats2half2_rn(q2, q3);
        uint2 pk;
        pk.x = *reinterpret_cast<uint32_t*>(&p0);
        pk.y = *reinterpret_cast<uint32_t*>(&p1);
        dst[g] = pk;
    }
}

// ===================== kernel 2: mma.sync fp16 GEMM =====================
// CTA 128x128x64, 4 warps (2m x 2n) each 64x64, 3-stage cp.async, 2 CTAs/SM.
// Bigger warp tile halves cross-warp LDSM re-reads (smem was co-limiting).
__global__ void __launch_bounds__(128, 2)
gemm_kernel(const float* __restrict__ bias, float* __restrict__ out) {
    extern __shared__ char smem[];
    const uint32_t sb = smem_u32(smem);
    const int tid  = threadIdx.x, lane = tid & 31, wid = tid >> 5;
    const int m0 = blockIdx.x * BM;
    const int n0 = blockIdx.y * BN;
    const int mw = (wid & 1) * 64;      // warp m offset
    const int nw = (wid >> 1) * 64;     // warp n offset

    // cp.async: per stage, A = 1024 granules of 16B (8/thread), B = 1024 (8/thread)
    const int rA = tid >> 3, gA = tid & 7;        // row 0..15 (+i*16), granule in row
    const uint32_t dSw = SWZ(rA, gA);             // row r+16: (r+16)&7 == r&7 -> same swizzle col
    const __half* srcA0 = g_A + (size_t)(m0 + rA) * KDIM + gA * 8;
    const __half* srcB0 = g_W + (size_t)(n0 + rA) * KDIM + gA * 8;
    const size_t rowSkip = (size_t)16 * KDIM;

    float acc[4][8][4];
#pragma unroll
    for (int i = 0; i < 4; ++i)
#pragma unroll
        for (int j = 0; j < 8; ++j)
#pragma unroll
            for (int k = 0; k < 4; ++k) acc[i][j][k] = 0.0f;

    // prologue: fill stages 0,1
#pragma unroll
    for (int s = 0; s < 2; ++s) {
        const uint32_t a = sb + s * STAGE_BYTES;
        const uint32_t b = a + 16384;
        const int ko = s * BK;
#pragma unroll
        for (int i = 0; i < 8; ++i) {
            CP_ASYNC16(a + dSw + i * 2048, srcA0 + i * rowSkip + ko);
            CP_ASYNC16(b + dSw + i * 2048, srcB0 + i * rowSkip + ko);
        }
        CP_COMMIT();
    }

    int rdSt = 0, wrSt = 2;   // read stage = it%3, write stage = (it+2)%3
    for (int it = 0; it < KIT; ++it) {
        CP_WAIT1();
        __syncthreads();

        if (it + 2 < KIT) {
            const uint32_t a = sb + wrSt * STAGE_BYTES;
            const uint32_t b = a + 16384;
            const int ko = (it + 2) * BK;
#pragma unroll
            for (int i = 0; i < 8; ++i) {
                CP_ASYNC16(a + dSw + i * 2048, srcA0 + i * rowSkip + ko);
                CP_ASYNC16(b + dSw + i * 2048, srcB0 + i * rowSkip + ko);
            }
        }
        CP_COMMIT();

        const uint32_t sA = sb + rdSt * STAGE_BYTES;
        const uint32_t sB = sA + 16384;

#pragma unroll
        for (int ks = 0; ks < 4; ++ks) {
            uint32_t aF[4][4], bF[4][4];
#pragma unroll
            for (int mt = 0; mt < 4; ++mt) {
                const int row = mw + mt * 16 + (lane & 15);
                const int g   = ks * 2 + (lane >> 4);
                LDSM4(aF[mt], sA + SWZ(row, g));
            }
#pragma unroll
            for (int nt = 0; nt < 4; ++nt) {
                const int row = nw + nt * 16 + (lane & 7) + ((lane >> 4) << 3);
                const int g   = ks * 2 + ((lane >> 3) & 1);
                LDSM4(bF[nt], sB + SWZ(row, g));
            }
#pragma unroll
            for (int mt = 0; mt < 4; ++mt)
#pragma unroll
                for (int nt = 0; nt < 4; ++nt) {
                    MMA16816(acc[mt][2 * nt],     aF[mt], bF[nt][0], bF[nt][1]);
                    MMA16816(acc[mt][2 * nt + 1], aF[mt], bF[nt][2], bF[nt][3]);
                }
        }
        // NO end-of-loop barrier: top-of-loop sync orders stage reads vs overwrite.

        rdSt = (rdSt == 2) ? 0 : rdSt + 1;
        wrSt = (wrSt == 2) ? 0 : wrSt + 1;
    }

    // epilogue: scale * acc + bias, direct float2 stores
#pragma unroll
    for (int mt = 0; mt < 4; ++mt) {
        const int m = m0 + mw + mt * 16 + (lane >> 2);
        const float s0 = g_scale[m];
        const float s1 = g_scale[m + 8];
#pragma unroll
        for (int nt = 0; nt < 8; ++nt) {
            const int n = n0 + nw + nt * 8 + (lane & 3) * 2;
            const float2 b2 = *reinterpret_cast<const float2*>(bias + n);
            float2 o0, o1;
            o0.x = acc[mt][nt][0] * s0 + b2.x;
            o0.y = acc[mt][nt][1] * s0 + b2.y;
            o1.x = acc[mt][nt][2] * s1 + b2.x;
            o1.y = acc[mt][nt][3] * s1 + b2.y;
            *reinterpret_cast<float2*>(out + (size_t)m * NDIM + n)       = o0;
            *reinterpret_cast<float2*>(out + (size_t)(m + 8) * NDIM + n) = o1;
        }
    }
}

// ===================== launch =====================
extern "C" void kernel_launch(void* const* d_in, const int* in_sizes, int n_in,
                              void* d_out, int out_size) {
    const float* x    = static_cast<const float*>(d_in[0]);
    const float* w    = static_cast<const float*>(d_in[1]);
    const float* bias = static_cast<const float*>(d_in[2]);
    const float* ss   = static_cast<const float*>(d_in[3]);
    float* out = static_cast<float*>(d_out);

    prep_kernel<<<MTOK + 1024, 128>>>(x, ss, w);

    cudaFuncSetAttribute(gemm_kernel, cudaFuncAttributeMaxDynamicSharedMemorySize, SMEM_GEMM);
    dim3 grid(MTOK / BM, NDIM / BN);   // 64 x 32
    gemm_kernel<<<grid, 128, SMEM_GEMM>>>(bias, out);
}

// round 16
// speedup vs baseline: 1.2790x; 1.0084x over previous
#include <cuda_runtime.h>
#include <cuda_fp16.h>
#include <cstdint>

// ===================== problem constants =====================
#define MTOK   8192
#define KDIM   4096
#define NDIM   4096
#define BM     128
#define BN     128
#define BK     64
#define KIT    (KDIM / BK)          // 64
#define STAGE_BYTES 32768           // A 16KB + B 16KB per stage
#define NSTAGE 3
#define SMEM_GEMM   (NSTAGE * STAGE_BYTES)   // 96 KB -> 2 CTAs/SM

// ===================== scratch (device globals; no runtime alloc) =====================
__device__ __half g_A[(size_t)MTOK * KDIM];   // quantized activations (exact ints in fp16)
__device__ __half g_W[(size_t)NDIM * KDIM];   // weights in fp16
__device__ float  g_scale[MTOK];              // per-token scale

// ===================== helpers =====================
__device__ __forceinline__ uint32_t smem_u32(const void* p) {
    uint32_t a;
    asm("{ .reg .u64 t; cvta.to.shared.u64 t, %1; cvt.u32.u64 %0, t; }" : "=r"(a) : "l"(p));
    return a;
}

// rows of 128B (64 halfs); XOR-swizzle the 8 16B granules by row&7 -> ldmatrix conflict-free
#define SWZ(row, g) ((uint32_t)((row) * 128 + ((((g) ^ ((row) & 7))) << 4)))

#define CP_ASYNC16(dst, src) \
    asm volatile("cp.async.cg.shared.global [%0], [%1], 16;" :: "r"(dst), "l"(src) : "memory")
#define CP_COMMIT() asm volatile("cp.async.commit_group;" ::: "memory")
#define CP_WAIT1()  asm volatile("cp.async.wait_group 1;" ::: "memory")

#define LDSM4(r, addr)                                                              \
    asm volatile("ldmatrix.sync.aligned.m8n8.x4.shared.b16 {%0,%1,%2,%3}, [%4];"    \
        : "=r"((r)[0]), "=r"((r)[1]), "=r"((r)[2]), "=r"((r)[3]) : "r"(addr))

#define MMA16816(d, a, b0, b1)                                                      \
    asm volatile("mma.sync.aligned.m16n8k16.row.col.f32.f16.f16.f32 "               \
        "{%0,%1,%2,%3},{%4,%5,%6,%7},{%8,%9},{%0,%1,%2,%3};"                        \
        : "+f"((d)[0]), "+f"((d)[1]), "+f"((d)[2]), "+f"((d)[3])                    \
        : "r"((a)[0]), "r"((a)[1]), "r"((a)[2]), "r"((a)[3]), "r"(b0), "r"(b1))

// load one k16 slice of fragments (8 LDSM.x4)
#define LOAD_FRAGS(Abuf, Bbuf, sA, sB, ks) do {                                     \
    _Pragma("unroll")                                                               \
    for (int mt = 0; mt < 4; ++mt) {                                                \
        const int row = mw + mt * 16 + (lane & 15);                                 \
        const int g   = (ks) * 2 + (lane >> 4);                                     \
        LDSM4((Abuf)[mt], (sA) + SWZ(row, g));                                      \
    }                                                                               \
    _Pragma("unroll")                                                               \
    for (int nt = 0; nt < 4; ++nt) {                                                \
        const int row = nw + nt * 16 + (lane & 7) + ((lane >> 4) << 3);             \
        const int g   = (ks) * 2 + ((lane >> 3) & 1);                               \
        LDSM4((Bbuf)[nt], (sB) + SWZ(row, g));                                      \
    }                                                                               \
} while (0)

#define DO_MMAS(Abuf, Bbuf) do {                                                    \
    _Pragma("unroll")                                                               \
    for (int mt = 0; mt < 4; ++mt)                                                  \
        _Pragma("unroll")                                                           \
        for (int nt = 0; nt < 4; ++nt) {                                            \
            MMA16816(acc[mt][2 * nt],     (Abuf)[mt], (Bbuf)[nt][0], (Bbuf)[nt][1]);\
            MMA16816(acc[mt][2 * nt + 1], (Abuf)[mt], (Bbuf)[nt][2], (Bbuf)[nt][3]);\
        }                                                                           \
} while (0)

// ===================== kernel 1: fused prep (activations + weights) =====================
// blocks [0, 8192): one token each (sparsity + absmax quant)
// blocks [8192, 9216): weight fp32->fp16, 4096 float4 per block
__global__ void __launch_bounds__(128) prep_kernel(const float* __restrict__ x,
                                                   const float* __restrict__ ss,
                                                   const float* __restrict__ w) {
    const int tid = threadIdx.x;

    if (blockIdx.x >= MTOK) {
        const int base = (blockIdx.x - MTOK) * 4096;
        uint2* dst = reinterpret_cast<uint2*>(g_W);
        const float4* src = reinterpret_cast<const float4*>(w);
#pragma unroll
        for (int i = 0; i < 32; ++i) {
            const int idx = base + i * 128 + tid;
            float4 v = src[idx];
            __half2 h0 = __floats2half2_rn(v.x, v.y);
            __half2 h1 = __floats2half2_rn(v.z, v.w);
            uint2 pk;
            pk.x = *reinterpret_cast<uint32_t*>(&h0);
            pk.y = *reinterpret_cast<uint32_t*>(&h1);
            dst[idx] = pk;
        }
        return;
    }

    __shared__ float red[4];
    const int t   = blockIdx.x;
    const int lid = tid & 31, wid = tid >> 5;

    const float4* xr  = reinterpret_cast<const float4*>(x + (size_t)t * KDIM);
    const float4* ssr = reinterpret_cast<const float4*>(ss);

    float4 kept[8];
    float kmax = 0.0f;
#pragma unroll
    for (int j = 0; j < 8; ++j) {
        const int g = j * 128 + tid;            // group id 0..1023
        float4 xv = xr[g];
        float4 sv = ssr[g];
        float mm[4] = { fabsf(xv.x) * sv.x, fabsf(xv.y) * sv.y,
                        fabsf(xv.z) * sv.z, fabsf(xv.w) * sv.w };
        int i1 = 0;
#pragma unroll
        for (int k = 1; k < 4; ++k) if (mm[k] < mm[i1]) i1 = k;
        int i2 = -1;
#pragma unroll
        for (int k = 0; k < 4; ++k) {
            if (k == i1) continue;
            if (i2 < 0 || mm[k] < mm[i2]) i2 = k;
        }
        float v[4] = { xv.x, xv.y, xv.z, xv.w };
        v[i1] = 0.0f; v[i2] = 0.0f;
        kept[j] = make_float4(v[0], v[1], v[2], v[3]);
        kmax = fmaxf(kmax, fmaxf(fmaxf(fabsf(v[0]), fabsf(v[1])),
                                 fmaxf(fabsf(v[2]), fabsf(v[3]))));
    }
#pragma unroll
    for (int off = 16; off; off >>= 1) kmax = fmaxf(kmax, __shfl_xor_sync(~0u, kmax, off));
    if (lid == 0) red[wid] = kmax;
    __syncthreads();
    const float amax  = fmaxf(fmaxf(red[0], red[1]), fmaxf(red[2], red[3]));
    const float denom = fmaxf(amax, 1e-5f);
    const float scale = denom / 127.0f;
    const float inv   = __fdiv_rn(127.0f, denom);
    if (tid == 0) g_scale[t] = scale;

    uint2* dst = reinterpret_cast<uint2*>(g_A + (size_t)t * KDIM);
#pragma unroll
    for (int j = 0; j < 8; ++j) {
        const int g = j * 128 + tid;
        float q0 = rintf(kept[j].x * inv);
        float q1 = rintf(kept[j].y * inv);
        float q2 = rintf(kept[j].z * inv);
        float q3 = rintf(kept[j].w * inv);
        __half2 p0 = __floats2half2_rn(q0, q1);
        __half2 p1 = __floats2half2_rn(q2, q3);
        uint2 pk;
        pk.x = *reinterpret_cast<uint32_t*>(&p0);
        pk.y = *reinterpret_cast<uint32_t*>(&p1);
        dst[g] = pk;
    }
}

// ===================== kernel 2: mma.sync fp16 GEMM =====================
// CTA 128x128x64, 4 warps (2m x 2n) each 64x64, 3-stage cp.async, 2 CTAs/SM.
// Register-level fragment double-buffering: LDSM(ks+1) overlaps MMA(ks).
__global__ void __launch_bounds__(128, 2)
gemm_kernel(const float* __restrict__ bias, float* __restrict__ out) {
    extern __shared__ char smem[];
    const uint32_t sb = smem_u32(smem);
    const int tid  = threadIdx.x, lane = tid & 31, wid = tid >> 5;
    const int m0 = blockIdx.x * BM;
    const int n0 = blockIdx.y * BN;
    const int mw = (wid & 1) * 64;      // warp m offset
    const int nw = (wid >> 1) * 64;     // warp n offset

    // cp.async: per stage, A = 1024 granules of 16B (8/thread), B = 1024 (8/thread)
    const int rA = tid >> 3, gA = tid & 7;        // row 0..15 (+i*16), granule in row
    const uint32_t dSw = SWZ(rA, gA);             // row r+16: (r+16)&7 == r&7 -> same swizzle col
    const __half* srcA0 = g_A + (size_t)(m0 + rA) * KDIM + gA * 8;
    const __half* srcB0 = g_W + (size_t)(n0 + rA) * KDIM + gA * 8;
    const size_t rowSkip = (size_t)16 * KDIM;

    float acc[4][8][4];
#pragma unroll
    for (int i = 0; i < 4; ++i)
#pragma unroll
        for (int j = 0; j < 8; ++j)
#pragma unroll
            for (int k = 0; k < 4; ++k) acc[i][j][k] = 0.0f;

    // prologue: fill stages 0,1
#pragma unroll
    for (int s = 0; s < 2; ++s) {
        const uint32_t a = sb + s * STAGE_BYTES;
        const uint32_t b = a + 16384;
        const int ko = s * BK;
#pragma unroll
        for (int i = 0; i < 8; ++i) {
            CP_ASYNC16(a + dSw + i * 2048, srcA0 + i * rowSkip + ko);
            CP_ASYNC16(b + dSw + i * 2048, srcB0 + i * rowSkip + ko);
        }
        CP_COMMIT();
    }

    uint32_t aF[2][4][4], bF[2][4][4];

    int rdSt = 0, wrSt = 2;   // read stage = it%3, write stage = (it+2)%3
    for (int it = 0; it < KIT; ++it) {
        CP_WAIT1();
        __syncthreads();

        if (it + 2 < KIT) {
            const uint32_t a = sb + wrSt * STAGE_BYTES;
            const uint32_t b = a + 16384;
            const int ko = (it + 2) * BK;
#pragma unroll
            for (int i = 0; i < 8; ++i) {
                CP_ASYNC16(a + dSw + i * 2048, srcA0 + i * rowSkip + ko);
                CP_ASYNC16(b + dSw + i * 2048, srcB0 + i * rowSkip + ko);
            }
        }
        CP_COMMIT();

        const uint32_t sA = sb + rdSt * STAGE_BYTES;
        const uint32_t sB = sA + 16384;

        // pipelined k-slices: LDSM(ks+1) issued before MMA(ks)
        LOAD_FRAGS(aF[0], bF[0], sA, sB, 0);
#pragma unroll
        for (int ks = 0; ks < 4; ++ks) {
            if (ks < 3) LOAD_FRAGS(aF[(ks + 1) & 1], bF[(ks + 1) & 1], sA, sB, ks + 1);
            DO_MMAS(aF[ks & 1], bF[ks & 1]);
        }
        // NO end-of-loop barrier: top-of-loop sync orders stage reads vs overwrite.

        rdSt = (rdSt == 2) ? 0 : rdSt + 1;
        wrSt = (wrSt == 2) ? 0 : wrSt + 1;
    }

    // epilogue: scale * acc + bias, direct float2 stores
#pragma unroll
    for (int mt = 0; mt < 4; ++mt) {
        const int m = m0 + mw + mt * 16 + (lane >> 2);
        const float s0 = g_scale[m];
        const float s1 = g_scale[m + 8];
#pragma unroll
        for (int nt = 0; nt < 8; ++nt) {
            const int n = n0 + nw + nt * 8 + (lane & 3) * 2;
            const float2 b2 = *reinterpret_cast<const float2*>(bias + n);
            float2 o0, o1;
            o0.x = acc[mt][nt][0] * s0 + b2.x;
            o0.y = acc[mt][nt][1] * s0 + b2.y;
            o1.x = acc[mt][nt][2] * s1 + b2.x;
            o1.y = acc[mt][nt][3] * s1 + b2.y;
            *reinterpret_cast<float2*>(out + (size_t)m * NDIM + n)       = o0;
            *reinterpret_cast<float2*>(out + (size_t)(m + 8) * NDIM + n) = o1;
        }
    }
}

// ===================== launch =====================
extern "C" void kernel_launch(void* const* d_in, const int* in_sizes, int n_in,
                              void* d_out, int out_size) {
    const float* x    = static_cast<const float*>(d_in[0]);
    const float* w    = static_cast<const float*>(d_in[1]);
    const float* bias = static_cast<const float*>(d_in[2]);
    const float* ss   = static_cast<const float*>(d_in[3]);
    float* out = static_cast<float*>(d_out);

    prep_kernel<<<MTOK + 1024, 128>>>(x, ss, w);

    cudaFuncSetAttribute(gemm_kernel, cudaFuncAttributeMaxDynamicSharedMemorySize, SMEM_GEMM);
    dim3 grid(MTOK / BM, NDIM / BN);   // 64 x 32
    gemm_kernel<<<grid, 128, SMEM_GEMM>>>(bias, out);
}